// round 9
// baseline (speedup 1.0000x reference)
#include <cuda_runtime.h>
#include <cuda_bf16.h>

// ZBL basis: per-edge screened Coulomb repulsion with polynomial cutoff,
// scatter-summed into receiver nodes.
//
// Inputs (metadata order):
//   d_in[0]: x               float32 [E, 1]   (E = 3,200,000)
//   d_in[1]: node_attrs      float32 [N, 10]  (N = 100,000)
//   d_in[2]: edge_index      int32   [2, E]
//   d_in[3]: atomic_numbers  int32   [10]
//   d_in[4]: covalent_radii  float32 [119]
// Output: V_ZBL float32 [N]
//
// HW model (R6-R8 validated): LSU/L1TEX wavefront throughput floor; RED
// scatter is the compulsory dominant term. This revision shaves the
// reducible LSU/instruction overhead:
//  - pair LUT = ONE float4 LDS.128 (8x bank-replicated: (idx*8+lane&7);
//    each 8-lane phase spans all 32 banks -> conflict-free, 4 wf minimum
//    anyway) instead of 3 scalar LDS + index math.
//  - smem 61.5KB/block -> 3 blocks x 512 thr/SM (48 warps), regs cap 42
//    so ptxas can hoist next-iteration loads.

#define MAX_NODES 100352            // >= N, even, multiple of 32
#define PACKED_N  (MAX_NODES / 2)   // nibble-packed element table
#define N_ELEMS   10
#define NPAIR     (N_ELEMS * N_ELEMS)
#define NT        512
#define EDGE_GRID 444               // 3 blocks/SM x 148 SMs: one full wave

__device__ unsigned char g_e4[PACKED_N];   // 2 nodes/byte: elem idx nibbles

__device__ __forceinline__ float ex2f(float a) {
    float r; asm("ex2.approx.f32 %0, %1;" : "=f"(r) : "f"(a)); return r;
}
__device__ __forceinline__ float frcpf(float a) {
    float r; asm("rcp.approx.f32 %0, %1;" : "=f"(r) : "f"(a)); return r;
}

// Predicated no-return global float add; no memory clobber (write-only out).
__device__ __forceinline__ void red_add_if(float* addr, float val, float rr) {
    asm volatile(
        "{\n\t"
        ".reg .pred p;\n\t"
        "setp.lt.f32 p, %1, 0f3F800000;\n\t"   // rr < 1.0f
        "@p red.global.add.f32 [%0], %2;\n\t"
        "}"
        :: "l"(addr), "f"(rr), "f"(val));
}

// ---------------------------------------------------------------------------
// Node prep: each thread handles TWO nodes -> one packed byte (no write race).
// Also zeros the output.
// ---------------------------------------------------------------------------
__global__ void node_prep_kernel(const float* __restrict__ attrs,
                                 float* __restrict__ out,
                                 int n_nodes, int out_n) {
    __shared__ float s[512 * N_ELEMS];      // 20KB staging
    int base = blockIdx.x * 512;            // node base (2 nodes per thread)
    int nloc = n_nodes - base;
    if (nloc > 512) nloc = 512;
    if (nloc > 0) {
        int total = nloc * N_ELEMS;
        const float* src = attrs + (size_t)base * N_ELEMS;
        int nv4 = total >> 2;
        const float4* s4 = (const float4*)src;
        float4* d4 = (float4*)s;
        for (int k = threadIdx.x; k < nv4; k += 256) d4[k] = s4[k];
        for (int k = (nv4 << 2) + threadIdx.x; k < total; k += 256)
            s[k] = src[k];
    }
    __syncthreads();

    int t = threadIdx.x;                     // handles local nodes 2t, 2t+1
    int n0 = 2 * t, n1 = 2 * t + 1;
    unsigned char packed = 0;
#pragma unroll
    for (int half = 0; half < 2; half++) {
        int nl = half ? n1 : n0;
        if (nl < nloc) {
            const float* a = s + nl * N_ELEMS;
            int best = 0;
            float bv = a[0];
#pragma unroll
            for (int j = 1; j < N_ELEMS; j++) {
                float v = a[j];
                if (v > bv) { bv = v; best = j; }
            }
            packed |= (unsigned char)(best << (half * 4));
        }
    }
    int byte_idx = (base >> 1) + t;
    if (n0 < nloc) g_e4[byte_idx] = packed;

    // zero outputs: 2 per thread
    int o0 = base + n0, o1 = base + n1;
    if (o0 < out_n) out[o0] = 0.0f;
    if (o1 < out_n) out[o1] = 0.0f;
}

// ---------------------------------------------------------------------------
// Edge kernel
// ---------------------------------------------------------------------------
__device__ __forceinline__ void process_edge(
    int s, int r, float xi, int lane8,
    const unsigned char* __restrict__ s_e4,
    const float4* __restrict__ s_lut,   // [(eu*10+ev)*8 + (lane&7)]
    float* __restrict__ out)
{
    int eu = (s_e4[s >> 1] >> ((s & 1) << 2)) & 15;
    int ev = (s_e4[r >> 1] >> ((r & 1) << 2)) & 15;
    float4 p = s_lut[((eu * N_ELEMS + ev) << 3) + lane8];
    // p = (inv_rmax, invA, pref, 0)

    float rr = xi * p.x;
    float t  = xi * p.y;

    // exp(-c*t) as ex2((-c*log2e)*t); constants folded at compile time
    const float K0 = -3.2f    * 1.44269504f;
    const float K1 = -0.9423f * 1.44269504f;
    const float K2 = -0.4028f * 1.44269504f;
    const float K3 = -0.2016f * 1.44269504f;
    float phi = 0.1818f  * ex2f(K0 * t)
              + 0.5099f  * ex2f(K1 * t)
              + 0.2802f  * ex2f(K2 * t)
              + 0.02817f * ex2f(K3 * t);

    // polynomial envelope, p=6: 1 - 28 r^6 + 48 r^7 - 21 r^8
    float r2 = rr * rr;
    float r3 = r2 * rr;
    float r6 = r3 * r3;
    float env = fmaf(-28.0f, r6, 1.0f);
    env = fmaf(48.0f, r6 * rr, env);
    env = fmaf(-21.0f, r6 * r2, env);

    float val = p.z * phi * frcpf(xi) * env;
    red_add_if(out + r, val, rr);
}

__global__ void __launch_bounds__(NT, 3)
edge_kernel(const float* __restrict__ x,
            const int* __restrict__ ei,
            const int* __restrict__ atomic_numbers,
            const float* __restrict__ radii_g,
            float* __restrict__ out,
            int n_edges, int n_nodes) {
    extern __shared__ char smem[];
    float4* s_lut = (float4*)smem;                  // NPAIR*8 float4 = 12.8KB
    unsigned char* s_e4 = (unsigned char*)(s_lut + NPAIR * 8);

    int tid = threadIdx.x;
    int lane8 = tid & 7;

    // Build 8x-replicated float4 pair LUT: entry e copy c at [e*8 + c].
    if (tid < NPAIR) {
        int i = tid / N_ELEMS, j = tid % N_ELEMS;
        int Zi = atomic_numbers[i], Zj = atomic_numbers[j];
        float Zif = (float)Zi, Zjf = (float)Zj;
        float irm = 1.0f / (radii_g[Zi] + radii_g[Zj]);
        float ia  = (powf(Zif, 0.3f) + powf(Zjf, 0.3f))
                    * (1.0f / (0.4543f * 0.529f));
        float pf  = 0.5f * 14.3996f * Zif * Zjf;
        float4 v = make_float4(irm, ia, pf, 0.0f);
        int base = tid << 3;
#pragma unroll
        for (int c = 0; c < 8; c++) s_lut[base + c] = v;
    }
    // Copy packed nibble table into smem (16B-wide, coalesced, L2-resident)
    {
        const uint4* ge = (const uint4*)g_e4;
        uint4* se = (uint4*)s_e4;
        int nvec = (((n_nodes + 1) >> 1) + 15) >> 4;
        for (int w = tid; w < nvec; w += NT) se[w] = ge[w];
    }
    __syncthreads();

    const int2*   si = (const int2*)ei;
    const int2*   ri = (const int2*)(ei + n_edges);
    const float2* x2 = (const float2*)x;
    int n2 = n_edges >> 1;

    // Block-balanced contiguous chunk; threads stride NT within it.
    int q   = n2 / gridDim.x;
    int rem = n2 - q * gridDim.x;
    int b   = blockIdx.x;
    int start = b * q + (b < rem ? b : rem);
    int end   = start + q + (b < rem ? 1 : 0);

    for (int g = start + tid; g < end; g += NT) {
        int2 ss = si[g];
        int2 rr = ri[g];
        float2 xx = x2[g];
        process_edge(ss.x, rr.x, xx.x, lane8, s_e4, s_lut, out);
        process_edge(ss.y, rr.y, xx.y, lane8, s_e4, s_lut, out);
    }
    // scalar tail (n_edges odd)
    for (int i = (n2 << 1) + blockIdx.x * NT + tid; i < n_edges;
         i += gridDim.x * NT) {
        process_edge(ei[i], ei[n_edges + i], x[i], lane8, s_e4, s_lut, out);
    }
}

extern "C" void kernel_launch(void* const* d_in, const int* in_sizes, int n_in,
                              void* d_out, int out_size) {
    const float* x              = (const float*)d_in[0];
    const float* node_attrs     = (const float*)d_in[1];
    const int*   edge_index     = (const int*)  d_in[2];
    const int*   atomic_numbers = (const int*)  d_in[3];
    const float* covalent_radii = (const float*)d_in[4];
    float* out = (float*)d_out;

    int n_edges = in_sizes[0];            // E
    int n_nodes = in_sizes[1] / N_ELEMS;  // N

    {
        // each block covers 512 nodes / 512 outputs
        int cover = n_nodes > out_size ? n_nodes : out_size;
        int blocks = (cover + 511) / 512;
        node_prep_kernel<<<blocks, 256>>>(node_attrs, out, n_nodes, out_size);
    }

    int smem_bytes = NPAIR * 8 * (int)sizeof(float4) + PACKED_N;  // ~61.5KB
    cudaFuncSetAttribute(edge_kernel,
                         cudaFuncAttributeMaxDynamicSharedMemorySize,
                         smem_bytes);
    // THREE blocks/SM x 148 SMs, one full wave
    edge_kernel<<<EDGE_GRID, NT, smem_bytes>>>(x, edge_index, atomic_numbers,
                                               covalent_radii, out,
                                               n_edges, n_nodes);
}